// round 2
// baseline (speedup 1.0000x reference)
#include <cuda_runtime.h>
#include <cuda_bf16.h>
#include <cstdint>

// ---------------------------------------------------------------------------
// MPEdgeNodeBlock: projections -> node segment-sum agg -> node MLP ->
//                  edge gather -> edge MLP.  All fp32.
// Sizes are compile-time constants matching the reference.
// ---------------------------------------------------------------------------
#define N_NODES 25000
#define N_EDGES 200000
#define IN_F    64
#define OUT_F   64
#define HDIM    192      // 3 * OUT_F

// -------------------- scratch (device globals; no runtime alloc) ------------
__device__ float g_Xr[N_NODES * HDIM];   // node agg / ping (real)
__device__ float g_Xi[N_NODES * HDIM];   // node agg / ping (imag)
__device__ float g_Xt[N_NODES * HDIM];   // node pong
__device__ float g_Yr[(size_t)N_EDGES * HDIM];  // edge agg / ping (real)
__device__ float g_Yi[(size_t)N_EDGES * HDIM];  // edge agg / ping (imag)
__device__ float g_Yt[(size_t)N_EDGES * HDIM];  // edge pong
__device__ int   g_row[N_EDGES];
__device__ int   g_col[N_EDGES];
__device__ int   g_is64;

// -------------------- edge_index dtype detection + conversion ---------------
// If the buffer is int64 (little-endian), every odd 32-bit word is the high
// half of a value in [0, 25000) -> zero.  If int32, odd words are random col
// indices; probability all 128 are zero is ~0.
__global__ void k_detect(const unsigned int* __restrict__ p) {
    if (threadIdx.x == 0) {
        int all_zero = 1;
        for (int i = 0; i < 128; ++i) {
            if (p[2 * i + 1] != 0u) { all_zero = 0; break; }
        }
        g_is64 = all_zero;
    }
}

__global__ void k_convert(const void* __restrict__ raw) {
    int e = blockIdx.x * blockDim.x + threadIdx.x;
    if (e >= N_EDGES) return;
    if (g_is64) {
        const long long* p = (const long long*)raw;
        g_row[e] = (int)p[2 * e];
        g_col[e] = (int)p[2 * e + 1];
    } else {
        const int* p = (const int*)raw;
        g_row[e] = p[2 * e];
        g_col[e] = p[2 * e + 1];
    }
}

// -------------------- zero node-agg buffers ---------------------------------
__global__ void k_zeroX() {
    int i = blockIdx.x * blockDim.x + threadIdx.x;
    if (i < N_NODES * HDIM) { g_Xr[i] = 0.f; g_Xi[i] = 0.f; }
}

// -------------------- generic fp32 GEMM: C = act(A @ W^T + b) ---------------
// A: M x K (row-major, lda), W: N x K (row-major, ld = K), C: M x N (ldc).
// BM=128, BN=64, BK=16, 256 threads, each thread computes 8x4.
// Grid: (ceil(M/128), N/64).
__global__ __launch_bounds__(256)
void k_gemm(const float* __restrict__ A, int M, int K, int lda,
            const float* __restrict__ W,
            const float* __restrict__ bias,
            const float* __restrict__ alphaPtr,   // null => no activation
            float* __restrict__ C, int ldc)
{
    const int BM = 128, BN = 64, BK = 16;
    __shared__ float As[BK][BM];
    __shared__ float Bs[BK][BN];

    const int bm  = blockIdx.x * BM;
    const int bn  = blockIdx.y * BN;
    const int tid = threadIdx.x;
    const int tx  = tid & 15;        // 0..15 -> 4 output cols each
    const int ty  = tid >> 4;        // 0..15 -> 8 output rows each

    float acc[8][4];
#pragma unroll
    for (int i = 0; i < 8; ++i)
#pragma unroll
        for (int j = 0; j < 4; ++j) acc[i][j] = 0.f;

    for (int k0 = 0; k0 < K; k0 += BK) {
        // ---- load A tile (transposed into As[k][m]) : 512 float4 ----
#pragma unroll
        for (int it = 0; it < 2; ++it) {
            int idx = tid + it * 256;          // 0..511
            int m   = idx >> 2;                // 0..127
            int kq  = (idx & 3) * 4;           // 0,4,8,12
            int gm  = bm + m;
            float4 v = make_float4(0.f, 0.f, 0.f, 0.f);
            if (gm < M)
                v = *reinterpret_cast<const float4*>(A + (size_t)gm * lda + k0 + kq);
            As[kq + 0][m] = v.x; As[kq + 1][m] = v.y;
            As[kq + 2][m] = v.z; As[kq + 3][m] = v.w;
        }
        // ---- load W tile (transposed into Bs[k][n]) : 256 float4 ----
        {
            int n  = tid >> 2;                 // 0..63
            int kq = (tid & 3) * 4;
            float4 v = *reinterpret_cast<const float4*>(
                W + (size_t)(bn + n) * K + k0 + kq);
            Bs[kq + 0][n] = v.x; Bs[kq + 1][n] = v.y;
            Bs[kq + 2][n] = v.z; Bs[kq + 3][n] = v.w;
        }
        __syncthreads();

#pragma unroll
        for (int k = 0; k < BK; ++k) {
            float a[8], b[4];
#pragma unroll
            for (int i = 0; i < 8; ++i) a[i] = As[k][ty * 8 + i];
#pragma unroll
            for (int j = 0; j < 4; ++j) b[j] = Bs[k][tx * 4 + j];
#pragma unroll
            for (int i = 0; i < 8; ++i)
#pragma unroll
                for (int j = 0; j < 4; ++j) acc[i][j] = fmaf(a[i], b[j], acc[i][j]);
        }
        __syncthreads();
    }

    // ---- epilogue: bias + optional leaky-relu, float4 stores ----
    const bool  act = (alphaPtr != nullptr);
    const float al  = act ? __ldg(alphaPtr) : 1.0f;
    const int   gn  = bn + tx * 4;
    const float4 bv = *reinterpret_cast<const float4*>(bias + gn);

#pragma unroll
    for (int i = 0; i < 8; ++i) {
        int gm = bm + ty * 8 + i;
        if (gm < M) {
            float4 o;
            o.x = acc[i][0] + bv.x;
            o.y = acc[i][1] + bv.y;
            o.z = acc[i][2] + bv.z;
            o.w = acc[i][3] + bv.w;
            if (act) {
                o.x = (o.x >= 0.f) ? o.x : al * o.x;
                o.y = (o.y >= 0.f) ? o.y : al * o.y;
                o.z = (o.z >= 0.f) ? o.z : al * o.z;
                o.w = (o.w >= 0.f) ? o.w : al * o.w;
            }
            *reinterpret_cast<float4*>(C + (size_t)gm * ldc + gn) = o;
        }
    }
}

// -------------------- node aggregation (segment-sum via atomics) ------------
// X[:, 64:128] += nr[col]   (per edge, scattered to row)
// X[:,128:192] += er[e]
__global__ void k_scatter() {
    int t = blockIdx.x * blockDim.x + threadIdx.x;
    if (t >= N_EDGES * IN_F) return;
    int e = t >> 6;
    int f = t & 63;
    int r = g_row[e];
    int c = g_col[e];

    float vnr = g_Xr[(size_t)c * HDIM + f];          // nr[col]
    float vni = g_Xi[(size_t)c * HDIM + f];
    float ver = g_Yr[(size_t)e * HDIM + f];          // er[e]
    float vei = g_Yi[(size_t)e * HDIM + f];

    atomicAdd(&g_Xr[(size_t)r * HDIM + 64  + f], vnr);
    atomicAdd(&g_Xr[(size_t)r * HDIM + 128 + f], ver);
    atomicAdd(&g_Xi[(size_t)r * HDIM + 64  + f], vni);
    atomicAdd(&g_Xi[(size_t)r * HDIM + 128 + f], vei);
}

// -------------------- edge gather: Y[:,64:128]=h[row], Y[:,128:192]=h[col] --
__global__ void k_gather(const float* __restrict__ hr,
                         const float* __restrict__ hi) {
    int t = blockIdx.x * blockDim.x + threadIdx.x;
    if (t >= N_EDGES * IN_F) return;
    int e = t >> 6;
    int f = t & 63;
    int r = g_row[e];
    int c = g_col[e];
    g_Yr[(size_t)e * HDIM + 64  + f] = hr[(size_t)r * OUT_F + f];
    g_Yr[(size_t)e * HDIM + 128 + f] = hr[(size_t)c * OUT_F + f];
    g_Yi[(size_t)e * HDIM + 64  + f] = hi[(size_t)r * OUT_F + f];
    g_Yi[(size_t)e * HDIM + 128 + f] = hi[(size_t)c * OUT_F + f];
}

// ---------------------------------------------------------------------------
static float* symaddr(const void* sym) {
    void* p = nullptr;
    cudaGetSymbolAddress(&p, sym);
    return (float*)p;
}

extern "C" void kernel_launch(void* const* d_in, const int* in_sizes, int n_in,
                              void* d_out, int out_size)
{
    const float* node_real = (const float*)d_in[0];
    const float* node_imag = (const float*)d_in[1];
    const float* edge_real = (const float*)d_in[2];
    const float* edge_imag = (const float*)d_in[3];
    const void*  edge_idx  = d_in[4];
    const float* Wn        = (const float*)d_in[5];
    const float* bn_       = (const float*)d_in[6];
    const float* We        = (const float*)d_in[7];
    const float* be_       = (const float*)d_in[8];
    const float* node_W    = (const float*)d_in[9];
    const float* node_b    = (const float*)d_in[10];
    const float* node_al   = (const float*)d_in[11];
    const float* node_oW   = (const float*)d_in[12];
    const float* node_ob   = (const float*)d_in[13];
    const float* edge_W    = (const float*)d_in[14];
    const float* edge_b    = (const float*)d_in[15];
    const float* edge_al   = (const float*)d_in[16];
    const float* edge_oW   = (const float*)d_in[17];
    const float* edge_ob   = (const float*)d_in[18];

    float* out  = (float*)d_out;
    float* hr   = out;
    float* hi   = out + (size_t)N_NODES * OUT_F;
    float* outr = out + 2 * (size_t)N_NODES * OUT_F;
    float* outi = outr + (size_t)N_EDGES * OUT_F;

    float* Xr = symaddr(g_Xr);
    float* Xi = symaddr(g_Xi);
    float* Xt = symaddr(g_Xt);
    float* Yr = symaddr(g_Yr);
    float* Yi = symaddr(g_Yi);
    float* Yt = symaddr(g_Yt);

    const int TPB = 256;
    const int gN  = (N_NODES + 127) / 128;   // 196
    const int gE  = (N_EDGES + 127) / 128;   // 1563

    // 1. edge index conversion
    k_detect<<<1, 32>>>((const unsigned int*)edge_idx);
    k_convert<<<(N_EDGES + TPB - 1) / TPB, TPB>>>(edge_idx);

    // 2. zero node agg buffers
    k_zeroX<<<(N_NODES * HDIM + TPB - 1) / TPB, TPB>>>();

    // 3. projections: nr/ni -> X[:,0:64], er/ei -> Y[:,0:64]
    k_gemm<<<dim3(gN, 1), TPB>>>(node_real, N_NODES, IN_F, IN_F, Wn, bn_, nullptr, Xr, HDIM);
    k_gemm<<<dim3(gN, 1), TPB>>>(node_imag, N_NODES, IN_F, IN_F, Wn, bn_, nullptr, Xi, HDIM);
    k_gemm<<<dim3(gE, 1), TPB>>>(edge_real, N_EDGES, IN_F, IN_F, We, be_, nullptr, Yr, HDIM);
    k_gemm<<<dim3(gE, 1), TPB>>>(edge_imag, N_EDGES, IN_F, IN_F, We, be_, nullptr, Yi, HDIM);

    // 4. node aggregation
    k_scatter<<<(N_EDGES * IN_F + TPB - 1) / TPB, TPB>>>();

    // 5. node MLP (real): Xr -> Xt -> Xr -> Xt -> hr
    k_gemm<<<dim3(gN, 3), TPB>>>(Xr, N_NODES, HDIM, HDIM, node_W,                node_b,           node_al,     Xt, HDIM);
    k_gemm<<<dim3(gN, 3), TPB>>>(Xt, N_NODES, HDIM, HDIM, node_W + 1 * HDIM * HDIM, node_b + HDIM,     node_al + 1, Xr, HDIM);
    k_gemm<<<dim3(gN, 3), TPB>>>(Xr, N_NODES, HDIM, HDIM, node_W + 2 * HDIM * HDIM, node_b + 2 * HDIM, node_al + 2, Xt, HDIM);
    k_gemm<<<dim3(gN, 1), TPB>>>(Xt, N_NODES, HDIM, HDIM, node_oW, node_ob, nullptr, hr, OUT_F);

    //    node MLP (imag): Xi -> Xt -> Xi -> Xt -> hi
    k_gemm<<<dim3(gN, 3), TPB>>>(Xi, N_NODES, HDIM, HDIM, node_W,                node_b,           node_al,     Xt, HDIM);
    k_gemm<<<dim3(gN, 3), TPB>>>(Xt, N_NODES, HDIM, HDIM, node_W + 1 * HDIM * HDIM, node_b + HDIM,     node_al + 1, Xi, HDIM);
    k_gemm<<<dim3(gN, 3), TPB>>>(Xi, N_NODES, HDIM, HDIM, node_W + 2 * HDIM * HDIM, node_b + 2 * HDIM, node_al + 2, Xt, HDIM);
    k_gemm<<<dim3(gN, 1), TPB>>>(Xt, N_NODES, HDIM, HDIM, node_oW, node_ob, nullptr, hi, OUT_F);

    // 6. edge gather (needs hr/hi from d_out)
    k_gather<<<(N_EDGES * IN_F + TPB - 1) / TPB, TPB>>>(hr, hi);

    // 7. edge MLP (real): Yr -> Yt -> Yr -> Yt -> outr
    k_gemm<<<dim3(gE, 3), TPB>>>(Yr, N_EDGES, HDIM, HDIM, edge_W,                edge_b,           edge_al,     Yt, HDIM);
    k_gemm<<<dim3(gE, 3), TPB>>>(Yt, N_EDGES, HDIM, HDIM, edge_W + 1 * HDIM * HDIM, edge_b + HDIM,     edge_al + 1, Yr, HDIM);
    k_gemm<<<dim3(gE, 3), TPB>>>(Yr, N_EDGES, HDIM, HDIM, edge_W + 2 * HDIM * HDIM, edge_b + 2 * HDIM, edge_al + 2, Yt, HDIM);
    k_gemm<<<dim3(gE, 1), TPB>>>(Yt, N_EDGES, HDIM, HDIM, edge_oW, edge_ob, nullptr, outr, OUT_F);

    //    edge MLP (imag)
    k_gemm<<<dim3(gE, 3), TPB>>>(Yi, N_EDGES, HDIM, HDIM, edge_W,                edge_b,           edge_al,     Yt, HDIM);
    k_gemm<<<dim3(gE, 3), TPB>>>(Yt, N_EDGES, HDIM, HDIM, edge_W + 1 * HDIM * HDIM, edge_b + HDIM,     edge_al + 1, Yi, HDIM);
    k_gemm<<<dim3(gE, 3), TPB>>>(Yi, N_EDGES, HDIM, HDIM, edge_W + 2 * HDIM * HDIM, edge_b + 2 * HDIM, edge_al + 2, Yt, HDIM);
    k_gemm<<<dim3(gE, 1), TPB>>>(Yt, N_EDGES, HDIM, HDIM, edge_oW, edge_ob, nullptr, outi, OUT_F);
}